// round 10
// baseline (speedup 1.0000x reference)
#include <cuda_runtime.h>
#include <cuda_fp16.h>
#include <math.h>
#include <stdint.h>

#define NXD 1024
#define NHD 1024
#define BD  8
#define TD  2048
#define NQKV 3072

// ---------------- scratch (device globals; allocation-free rule) ------------
__device__ __half g_Xh[BD * TD * NXD];               // 32 MiB
__device__ __half g_Wh[4u * NHD * NXD];              // 8 MiB (Wq,Wk,Wv,Wo stacked)
__device__ __half g_QKV[(size_t)BD * TD * NQKV];     // 96 MiB ([M,3072]: Q|K|V)
__device__ float  g_S [(size_t)BD * TD * TD];        // 128 MiB (f32 scores)
__device__ __half g_Ph[(size_t)BD * TD * TD];        // 64 MiB (half probs)
__device__ __half g_Ah[BD * TD * NHD];               // 32 MiB

// ---------------- helpers ----------------------------------------------
__device__ __forceinline__ uint32_t smem_u32(const void* p) {
    uint32_t a;
    asm("{ .reg .u64 t; cvta.to.shared.u64 t, %1; cvt.u32.u64 %0, t; }"
        : "=r"(a) : "l"(p));
    return a;
}
__device__ __forceinline__ void cp_async16(uint32_t dst, const void* src) {
    asm volatile("cp.async.cg.shared.global [%0], [%1], 16;"
                 :: "r"(dst), "l"(src) : "memory");
}
__device__ __forceinline__ void mma_f16(float c[4], const uint32_t a[4], const uint32_t b[2]) {
    asm volatile(
        "mma.sync.aligned.m16n8k16.row.col.f32.f16.f16.f32 "
        "{%0,%1,%2,%3}, {%4,%5,%6,%7}, {%8,%9}, {%0,%1,%2,%3};"
        : "+f"(c[0]), "+f"(c[1]), "+f"(c[2]), "+f"(c[3])
        : "r"(a[0]), "r"(a[1]), "r"(a[2]), "r"(a[3]),
          "r"(b[0]), "r"(b[1]));
}
__device__ __forceinline__ void ldsm_x4(uint32_t r[4], uint32_t addr) {
    asm volatile("ldmatrix.sync.aligned.m8n8.x4.shared.b16 {%0,%1,%2,%3}, [%4];"
                 : "=r"(r[0]), "=r"(r[1]), "=r"(r[2]), "=r"(r[3]) : "r"(addr));
}
__device__ __forceinline__ void ldsm_x4_t(uint32_t r[4], uint32_t addr) {
    asm volatile("ldmatrix.sync.aligned.m8n8.x4.trans.shared.b16 {%0,%1,%2,%3}, [%4];"
                 : "=r"(r[0]), "=r"(r[1]), "=r"(r[2]), "=r"(r[3]) : "r"(addr));
}

// ---------------------------------------------------------------------------
// NT GEMM: C[M,N] = alpha * A[M,K] * B[N,K]^T  (half in; lda/ldb row strides)
// CTA 128x128, BK=64, 256 threads, warp tile 64x32, 3-stage cp.async,
// 2 CTAs/SM. out_half selects __half vs float C (ldc == N).
// ---------------------------------------------------------------------------
#define LROWH 72                               // 64 + 8 pad halves
#define STG_NT ((128 + 128) * LROWH)
#define NT_SMEM (3 * STG_NT * 2)               // 110592 B

__global__ __launch_bounds__(256, 2)
void gemm_h(const __half* __restrict__ Ag, const __half* __restrict__ Bg,
            void* __restrict__ Cg, int M, int N, int K, int lda, int ldb,
            float alpha, int out_half, size_t sA, size_t sB, size_t sC)
{
    extern __shared__ __half sm[];
    const uint32_t sbase = smem_u32(sm);

    const int tid  = threadIdx.x;
    const int wid  = tid >> 5;
    const int lane = tid & 31;
    const int wm   = wid >> 2;
    const int wn   = wid & 3;
    const int g    = lane >> 2;
    const int tig  = lane & 3;
    const int l7 = lane & 7;
    const int t4 = lane >> 3;

    const __half* Ab = Ag + blockIdx.z * sA + (size_t)blockIdx.y * 128 * lda;
    const __half* Bb = Bg + blockIdx.z * sB + (size_t)blockIdx.x * 128 * ldb;

    float acc[4][4][4];
#pragma unroll
    for (int i = 0; i < 4; i++)
#pragma unroll
        for (int j = 0; j < 4; j++)
#pragma unroll
            for (int r = 0; r < 4; r++) acc[i][j][r] = 0.f;

    const int nk = K >> 6;

    auto load_stage = [&](int js) {
        uint32_t stH = (uint32_t)((js % 3) * STG_NT);
        const __half* ga = Ab + js * 64;
        const __half* gb = Bb + js * 64;
#pragma unroll
        for (int i = 0; i < 8; i++) {
            int c   = tid + i * 256;
            int row = c >> 3;                 // 0..255
            int fh  = (c & 7) << 3;
            uint32_t d = sbase + 2u * (stH + row * LROWH + fh);
            if (i < 4)  cp_async16(d, ga + (size_t)row * lda + fh);
            else        cp_async16(d, gb + (size_t)(row - 128) * ldb + fh);
        }
        asm volatile("cp.async.commit_group;" ::: "memory");
    };

    load_stage(0);
    load_stage(1);

    const uint32_t aoff = (uint32_t)((wm * 64 + ((t4 & 1) << 3) + l7) * LROWH
                                     + ((t4 >> 1) << 3));
    uint32_t boff[2];
#pragma unroll
    for (int jj = 0; jj < 2; jj++)
        boff[jj] = (uint32_t)((wn * 32 + jj * 16 + ((t4 >> 1) << 3) + l7) * LROWH
                              + ((t4 & 1) << 3));

    for (int ks = 0; ks < nk; ks++) {
        asm volatile("cp.async.wait_group 1;" ::: "memory");
        __syncthreads();

        const uint32_t saA = sbase + 2u * (uint32_t)((ks % 3) * STG_NT);
        const uint32_t saB = saA + 2u * 128 * LROWH;

        uint32_t af[4][4], bf[2][4];
        auto ldfrag = [&](uint32_t kk) {
#pragma unroll
            for (int i = 0; i < 4; i++)
                ldsm_x4(af[i], saA + 2u * (aoff + i * 16 * LROWH + kk));
#pragma unroll
            for (int jj = 0; jj < 2; jj++)
                ldsm_x4_t ? (void)0 : (void)0, ldsm_x4(bf[jj], saB + 2u * (boff[jj] + kk));
        };
        auto do_mma = [&]() {
#pragma unroll
            for (int i = 0; i < 4; i++)
#pragma unroll
                for (int j = 0; j < 4; j++)
                    mma_f16(acc[i][j], af[i], &bf[j >> 1][(j & 1) * 2]);
        };

        // LDSM first, then stage loads, then MMAs (avoid cp.async issue delay)
        ldfrag(0);
        if (ks + 2 < nk) load_stage(ks + 2);
        else asm volatile("cp.async.commit_group;" ::: "memory");  // empty group keeps wait invariant
        do_mma();
#pragma unroll
        for (int k16 = 1; k16 < 4; k16++) {
            ldfrag((uint32_t)(k16 * 16));
            do_mma();
        }
    }

    // Epilogue (ldc == N)
#pragma unroll
    for (int i = 0; i < 4; i++) {
        size_t row0 = (size_t)blockIdx.y * 128 + wm * 64 + i * 16 + g;
        size_t col  = (size_t)blockIdx.x * 128 + wn * 32 + tig * 2;
        if (out_half) {
            __half* C0 = (__half*)Cg + blockIdx.z * sC + row0 * N + col;
            __half* C1 = C0 + 8 * (size_t)N;
#pragma unroll
            for (int j = 0; j < 4; j++) {
                *(__half2*)(C0 + j * 8) = __float22half2_rn(
                    make_float2(acc[i][j][0] * alpha, acc[i][j][1] * alpha));
                *(__half2*)(C1 + j * 8) = __float22half2_rn(
                    make_float2(acc[i][j][2] * alpha, acc[i][j][3] * alpha));
            }
        } else {
            float* C0 = (float*)Cg + blockIdx.z * sC + row0 * N + col;
            float* C1 = C0 + 8 * (size_t)N;
#pragma unroll
            for (int j = 0; j < 4; j++) {
                *(float2*)(C0 + j * 8) =
                    make_float2(acc[i][j][0] * alpha, acc[i][j][1] * alpha);
                *(float2*)(C1 + j * 8) =
                    make_float2(acc[i][j][2] * alpha, acc[i][j][3] * alpha);
            }
        }
    }
}

// ---------------------------------------------------------------------------
// NN GEMM: C[M,N] = A[M,K] * B[K,N]  (half in, half out; B n-contiguous).
// B fragments via ldmatrix.trans. Same tiling/pipeline as NT.
// ---------------------------------------------------------------------------
#define LROWB 136                              // 128 + 8 pad halves
#define STG_NN (128 * LROWH + 64 * LROWB)      // 17920 halves
#define NN_SMEM (3 * STG_NN * 2)               // 107520 B

__global__ __launch_bounds__(256, 2)
void gemm_h_nn(const __half* __restrict__ Ag, const __half* __restrict__ Bg,
               __half* __restrict__ Cg, int M, int N, int K, int lda, int ldb,
               size_t sA, size_t sB, size_t sC)
{
    extern __shared__ __half sm[];
    const uint32_t sbase = smem_u32(sm);

    const int tid  = threadIdx.x;
    const int wid  = tid >> 5;
    const int lane = tid & 31;
    const int wm   = wid >> 2;
    const int wn   = wid & 3;
    const int g    = lane >> 2;
    const int tig  = lane & 3;
    const int l7 = lane & 7;
    const int t4 = lane >> 3;

    const __half* Ab = Ag + blockIdx.z * sA + (size_t)blockIdx.y * 128 * lda;
    const __half* Bb = Bg + blockIdx.z * sB + (size_t)blockIdx.x * 128;  // n offset

    float acc[4][4][4];
#pragma unroll
    for (int i = 0; i < 4; i++)
#pragma unroll
        for (int j = 0; j < 4; j++)
#pragma unroll
            for (int r = 0; r < 4; r++) acc[i][j][r] = 0.f;

    const int nk = K >> 6;

    auto load_stage = [&](int js) {
        uint32_t stH = (uint32_t)((js % 3) * STG_NN);
        const __half* ga = Ab + js * 64;
#pragma unroll
        for (int i = 0; i < 8; i++) {
            int c = tid + i * 256;
            if (i < 4) {
                int row = c >> 3;                 // 0..127
                int fh  = (c & 7) << 3;
                cp_async16(sbase + 2u * (stH + row * LROWH + fh),
                           ga + (size_t)row * lda + fh);
            } else {
                int cb  = c - 1024;
                int row = cb >> 4;                // 0..63 (k-rows)
                int fh  = (cb & 15) << 3;         // 0..120 (n)
                cp_async16(sbase + 2u * (stH + 128 * LROWH + row * LROWB + fh),
                           Bb + (size_t)(js * 64 + row) * ldb + fh);
            }
        }
        asm volatile("cp.async.commit_group;" ::: "memory");
    };

    load_stage(0);
    load_stage(1);

    const uint32_t aoff = (uint32_t)((wm * 64 + ((t4 & 1) << 3) + l7) * LROWH
                                     + ((t4 >> 1) << 3));
    // trans-B tiles: m0=(k,n) m1=(k+8,n) m2=(k,n+8) m3=(k+8,n+8)
    uint32_t boff[2];
#pragma unroll
    for (int jj = 0; jj < 2; jj++)
        boff[jj] = (uint32_t)((((t4 & 1) << 3) + l7) * LROWB
                              + wn * 32 + jj * 16 + ((t4 >> 1) << 3));

    for (int ks = 0; ks < nk; ks++) {
        asm volatile("cp.async.wait_group 1;" ::: "memory");
        __syncthreads();

        const uint32_t saA = sbase + 2u * (uint32_t)((ks % 3) * STG_NN);
        const uint32_t saB = saA + 2u * 128 * LROWH;

        uint32_t af[4][4], bf[2][4];
        auto ldfrag = [&](uint32_t kk) {
#pragma unroll
            for (int i = 0; i < 4; i++)
                ldsm_x4(af[i], saA + 2u * (aoff + i * 16 * LROWH + kk));
#pragma unroll
            for (int jj = 0; jj < 2; jj++)
                ldsm_x4_t(bf[jj], saB + 2u * (boff[jj] + kk * LROWB));
        };
        auto do_mma = [&]() {
#pragma unroll
            for (int i = 0; i < 4; i++)
#pragma unroll
                for (int j = 0; j < 4; j++)
                    mma_f16(acc[i][j], af[i], &bf[j >> 1][(j & 1) * 2]);
        };

        ldfrag(0);
        if (ks + 2 < nk) load_stage(ks + 2);
        else asm volatile("cp.async.commit_group;" ::: "memory");
        do_mma();
#pragma unroll
        for (int k16 = 1; k16 < 4; k16++) {
            ldfrag((uint32_t)(k16 * 16));
            do_mma();
        }
    }

#pragma unroll
    for (int i = 0; i < 4; i++) {
        size_t row0 = (size_t)blockIdx.y * 128 + wm * 64 + i * 16 + g;
        size_t col  = (size_t)blockIdx.x * 128 + wn * 32 + tig * 2;
        __half* C0 = Cg + blockIdx.z * sC + row0 * N + col;
        __half* C1 = C0 + 8 * (size_t)N;
#pragma unroll
        for (int j = 0; j < 4; j++) {
            *(__half2*)(C0 + j * 8) = __float22half2_rn(
                make_float2(acc[i][j][0], acc[i][j][1]));
            *(__half2*)(C1 + j * 8) = __float22half2_rn(
                make_float2(acc[i][j][2], acc[i][j][3]));
        }
    }
}

// ---------------------------------------------------------------------------
__global__ __launch_bounds__(256) void cvt_h_kernel(
    const float* __restrict__ in, __half* __restrict__ out, int n4)
{
    int i = blockIdx.x * blockDim.x + threadIdx.x;
    if (i < n4) {
        float4 v = ((const float4*)in)[i];
        __half2 lo = __float22half2_rn(make_float2(v.x, v.y));
        __half2 hi = __float22half2_rn(make_float2(v.z, v.w));
        *(uint2*)(out + 4 * (size_t)i) =
            make_uint2(*(uint32_t*)&lo, *(uint32_t*)&hi);
    }
}

__global__ __launch_bounds__(256) void cvt4_h_kernel(
    const float* __restrict__ w0, const float* __restrict__ w1,
    const float* __restrict__ w2, const float* __restrict__ w3,
    __half* __restrict__ out, int n4)
{
    int i = blockIdx.x * blockDim.x + threadIdx.x;
    if (i < 4 * n4) {
        int sel = i / n4, off = i - sel * n4;
        const float* src = (sel == 0) ? w0 : (sel == 1) ? w1 : (sel == 2) ? w2 : w3;
        float4 v = ((const float4*)src)[off];
        __half2 lo = __float22half2_rn(make_float2(v.x, v.y));
        __half2 hi = __float22half2_rn(make_float2(v.z, v.w));
        *(uint2*)(out + 4 * (size_t)i) =
            make_uint2(*(uint32_t*)&lo, *(uint32_t*)&hi);
    }
}

// ---------------------------------------------------------------------------
__global__ __launch_bounds__(256) void softmax_rows(
    const float* __restrict__ S, __half* __restrict__ P)
{
    const float* row = S + (size_t)blockIdx.x * TD;
    __half* prow = P + (size_t)blockIdx.x * TD;
    __shared__ float red[256];
    const int tid = threadIdx.x;

    float4 v0 = *(const float4*)(row + tid * 8);
    float4 v1 = *(const float4*)(row + tid * 8 + 4);
    float v[8] = {v0.x, v0.y, v0.z, v0.w, v1.x, v1.y, v1.z, v1.w};

    float m = -INFINITY;
#pragma unroll
    for (int i = 0; i < 8; i++) m = fmaxf(m, v[i]);
    red[tid] = m;
    __syncthreads();
    for (int s = 128; s > 0; s >>= 1) {
        if (tid < s) red[tid] = fmaxf(red[tid], red[tid + s]);
        __syncthreads();
    }
    m = red[0];
    __syncthreads();

    float sum = 0.f;
#pragma unroll
    for (int i = 0; i < 8; i++) {
        v[i] = __expf(v[i] - m);
        sum += v[i];
    }
    red[tid] = sum;
    __syncthreads();
    for (int s = 128; s > 0; s >>= 1) {
        if (tid < s) red[tid] += red[tid + s];
        __syncthreads();
    }
    float inv = 1.f / red[0];
    __half2 h[4];
#pragma unroll
    for (int i = 0; i < 4; i++)
        h[i] = __float22half2_rn(make_float2(v[2 * i] * inv, v[2 * i + 1] * inv));
    *(uint2*)(prow + tid * 8) =
        make_uint2(*(uint32_t*)&h[0], *(uint32_t*)&h[1]);
    *(uint2*)(prow + tid * 8 + 4) =
        make_uint2(*(uint32_t*)&h[2], *(uint32_t*)&h[3]);
}

// ---------------------------------------------------------------------------
extern "C" void kernel_launch(void* const* d_in, const int* in_sizes, int n_in,
                              void* d_out, int out_size)
{
    const float* x   = (const float*)d_in[0];
    const float* W_q = (const float*)d_in[1];
    const float* W_k = (const float*)d_in[2];
    const float* W_v = (const float*)d_in[3];
    const float* W_o = (const float*)d_in[4];
    float* out = (float*)d_out;

    __half* Xh;  cudaGetSymbolAddress((void**)&Xh,  g_Xh);
    __half* Wh;  cudaGetSymbolAddress((void**)&Wh,  g_Wh);
    __half* QKV; cudaGetSymbolAddress((void**)&QKV, g_QKV);
    float*  S;   cudaGetSymbolAddress((void**)&S,   g_S);
    __half* Ph;  cudaGetSymbolAddress((void**)&Ph,  g_Ph);
    __half* Ah;  cudaGetSymbolAddress((void**)&Ah,  g_Ah);

    cudaFuncSetAttribute(gemm_h, cudaFuncAttributeMaxDynamicSharedMemorySize, NT_SMEM);
    cudaFuncSetAttribute(gemm_h_nn, cudaFuncAttributeMaxDynamicSharedMemorySize, NN_SMEM);

    const int M = BD * TD;                        // 16384
    const float scale = 1.0f / sqrtf((float)TD);
    const size_t WN = (size_t)NHD * NXD;

    cvt_h_kernel<<<(M * NXD / 4 + 255) / 256, 256>>>(x, Xh, M * NXD / 4);
    cvt4_h_kernel<<<(int)(4 * (WN / 4) + 255) / 256, 256>>>(
        W_q, W_k, W_v, W_o, Wh, (int)(WN / 4));

    // QKV = Xh @ [Wq;Wk;Wv]^T   [16384, 3072] (half)
    {
        dim3 g(NQKV / 128, M / 128, 1);
        gemm_h<<<g, 256, NT_SMEM>>>(Xh, Wh, QKV, M, NQKV, NXD, NXD, NXD,
                                    1.f, 1, 0, 0, 0);
    }
    // S[b] = (Q_b @ K_b^T) / sqrt(T)   (f32)
    {
        dim3 g(TD / 128, TD / 128, BD);
        gemm_h<<<g, 256, NT_SMEM>>>(QKV + 0, QKV + NHD, S, TD, TD, NHD,
                                    NQKV, NQKV, scale, 0,
                                    (size_t)TD * NQKV, (size_t)TD * NQKV,
                                    (size_t)TD * TD);
    }
    softmax_rows<<<BD * TD, 256>>>(S, Ph);

    // Ah[b] = Ph_b @ V_b   (NN: V n-contiguous inside QKV)
    {
        dim3 g(NHD / 128, TD / 128, BD);
        gemm_h_nn<<<g, 256, NN_SMEM>>>(Ph, QKV + 2 * NHD, Ah, TD, NHD, TD,
                                       TD, NQKV,
                                       (size_t)TD * TD, (size_t)TD * NQKV,
                                       (size_t)TD * NHD);
    }
    // out = Ah @ Wo^T   (f32)
    {
        dim3 g(NHD / 128, M / 128, 1);
        gemm_h<<<g, 256, NT_SMEM>>>(Ah, Wh + 3 * WN, out, M, NHD, NHD,
                                    NHD, NHD, 1.f, 0, 0, 0, 0);
    }
}

// round 11
// speedup vs baseline: 1.0337x; 1.0337x over previous
#include <cuda_runtime.h>
#include <cuda_fp16.h>
#include <math.h>
#include <stdint.h>

#define NXD 1024
#define NHD 1024
#define BD  8
#define TD  2048
#define NQKV 3072

// ---------------- scratch (device globals; allocation-free rule) ------------
__device__ __half g_Xh[BD * TD * NXD];               // 32 MiB
__device__ __half g_Wh[4u * NHD * NXD];              // 8 MiB (Wq,Wk,Wv,Wo stacked)
__device__ __half g_Qh[BD * TD * NHD];               // 32 MiB
__device__ __half g_Kh[BD * TD * NHD];               // 32 MiB
__device__ __half g_Vh[BD * TD * NHD];               // 32 MiB (natural layout)
__device__ float  g_S [(size_t)BD * TD * TD];        // 128 MiB (f32 scores)
__device__ __half g_Ph[(size_t)BD * TD * TD];        // 64 MiB (half probs)
__device__ __half g_Ah[BD * TD * NHD];               // 32 MiB

// ---------------- helpers ----------------------------------------------
__device__ __forceinline__ uint32_t smem_u32(const void* p) {
    uint32_t a;
    asm("{ .reg .u64 t; cvta.to.shared.u64 t, %1; cvt.u32.u64 %0, t; }"
        : "=r"(a) : "l"(p));
    return a;
}
__device__ __forceinline__ void cp_async16(uint32_t dst, const void* src) {
    asm volatile("cp.async.cg.shared.global [%0], [%1], 16;"
                 :: "r"(dst), "l"(src) : "memory");
}
__device__ __forceinline__ void mma_f16(float c[4], const uint32_t a[4], const uint32_t b[2]) {
    asm volatile(
        "mma.sync.aligned.m16n8k16.row.col.f32.f16.f16.f32 "
        "{%0,%1,%2,%3}, {%4,%5,%6,%7}, {%8,%9}, {%0,%1,%2,%3};"
        : "+f"(c[0]), "+f"(c[1]), "+f"(c[2]), "+f"(c[3])
        : "r"(a[0]), "r"(a[1]), "r"(a[2]), "r"(a[3]),
          "r"(b[0]), "r"(b[1]));
}
__device__ __forceinline__ void ldsm_x4(uint32_t r[4], uint32_t addr) {
    asm volatile("ldmatrix.sync.aligned.m8n8.x4.shared.b16 {%0,%1,%2,%3}, [%4];"
                 : "=r"(r[0]), "=r"(r[1]), "=r"(r[2]), "=r"(r[3]) : "r"(addr));
}
__device__ __forceinline__ void ldsm_x4_t(uint32_t r[4], uint32_t addr) {
    asm volatile("ldmatrix.sync.aligned.m8n8.x4.trans.shared.b16 {%0,%1,%2,%3}, [%4];"
                 : "=r"(r[0]), "=r"(r[1]), "=r"(r[2]), "=r"(r[3]) : "r"(addr));
}

// ---------------------------------------------------------------------------
// NT GEMM: C[M,N] = alpha * A[M,K] * B[N,K]^T  (half in; lda/ldb row strides)
// CTA 128x128, BK=64, 256 threads, warp tile 64x32, 3-stage cp.async,
// 2 CTAs/SM. out_half selects __half vs float C.
// split!=0: QKV mode — blockIdx.x>>3 selects Cq/Ck/Cv (each [M,1024]),
// column tile = blockIdx.x&7. Else writes Cg with ldc=N.
// ---------------------------------------------------------------------------
#define LROWH 72                               // 64 + 8 pad halves
#define STG_NT ((128 + 128) * LROWH)
#define NT_SMEM (3 * STG_NT * 2)               // 110592 B

__global__ __launch_bounds__(256, 2)
void gemm_h(const __half* __restrict__ Ag, const __half* __restrict__ Bg,
            void* __restrict__ Cg,
            __half* __restrict__ Cq, __half* __restrict__ Ck,
            __half* __restrict__ Cv, int split,
            int M, int N, int K, int lda, int ldb,
            float alpha, int out_half, size_t sA, size_t sB, size_t sC)
{
    extern __shared__ __half sm[];
    const uint32_t sbase = smem_u32(sm);

    const int tid  = threadIdx.x;
    const int wid  = tid >> 5;
    const int lane = tid & 31;
    const int wm   = wid >> 2;
    const int wn   = wid & 3;
    const int g    = lane >> 2;
    const int tig  = lane & 3;
    const int l7 = lane & 7;
    const int t4 = lane >> 3;

    const __half* Ab = Ag + blockIdx.z * sA + (size_t)blockIdx.y * 128 * lda;
    const __half* Bb = Bg + blockIdx.z * sB + (size_t)blockIdx.x * 128 * ldb;

    float acc[4][4][4];
#pragma unroll
    for (int i = 0; i < 4; i++)
#pragma unroll
        for (int j = 0; j < 4; j++)
#pragma unroll
            for (int r = 0; r < 4; r++) acc[i][j][r] = 0.f;

    const int nk = K >> 6;

    auto load_stage = [&](int js) {
        uint32_t stH = (uint32_t)((js % 3) * STG_NT);
        const __half* ga = Ab + js * 64;
        const __half* gb = Bb + js * 64;
#pragma unroll
        for (int i = 0; i < 8; i++) {
            int c   = tid + i * 256;
            int row = c >> 3;                 // 0..255
            int fh  = (c & 7) << 3;
            uint32_t d = sbase + 2u * (stH + row * LROWH + fh);
            if (i < 4)  cp_async16(d, ga + (size_t)row * lda + fh);
            else        cp_async16(d, gb + (size_t)(row - 128) * ldb + fh);
        }
        asm volatile("cp.async.commit_group;" ::: "memory");
    };

    load_stage(0);
    load_stage(1);

    const uint32_t aoff = (uint32_t)((wm * 64 + ((t4 & 1) << 3) + l7) * LROWH
                                     + ((t4 >> 1) << 3));
    uint32_t boff[2];
#pragma unroll
    for (int jj = 0; jj < 2; jj++)
        boff[jj] = (uint32_t)((wn * 32 + jj * 16 + ((t4 >> 1) << 3) + l7) * LROWH
                              + ((t4 & 1) << 3));

    for (int ks = 0; ks < nk; ks++) {
        asm volatile("cp.async.wait_group 1;" ::: "memory");
        __syncthreads();

        const uint32_t saA = sbase + 2u * (uint32_t)((ks % 3) * STG_NT);
        const uint32_t saB = saA + 2u * 128 * LROWH;

        uint32_t af[4][4], bf[2][4];
        auto ldfrag = [&](uint32_t kk) {
#pragma unroll
            for (int i = 0; i < 4; i++)
                ldsm_x4(af[i], saA + 2u * (aoff + i * 16 * LROWH + kk));
#pragma unroll
            for (int jj = 0; jj < 2; jj++)
                ldsm_x4(bf[jj], saB + 2u * (boff[jj] + kk));
        };
        auto do_mma = [&]() {
#pragma unroll
            for (int i = 0; i < 4; i++)
#pragma unroll
                for (int j = 0; j < 4; j++)
                    mma_f16(acc[i][j], af[i], &bf[j >> 1][(j & 1) * 2]);
        };

        // LDSM first, then next stage loads, then MMAs
        ldfrag(0);
        if (ks + 2 < nk) load_stage(ks + 2);
        else asm volatile("cp.async.commit_group;" ::: "memory");  // keep wait invariant
        do_mma();
#pragma unroll
        for (int k16 = 1; k16 < 4; k16++) {
            ldfrag((uint32_t)(k16 * 16));
            do_mma();
        }
    }

    // Epilogue
    int  Nout = N;
    int  bxl  = blockIdx.x;
    void* Cbase = Cg;
    if (split) {
        int sel = blockIdx.x >> 3;
        bxl = blockIdx.x & 7;
        Nout = NHD;
        Cbase = (sel == 0) ? (void*)Cq : (sel == 1) ? (void*)Ck : (void*)Cv;
    }
#pragma unroll
    for (int i = 0; i < 4; i++) {
        size_t row0 = (size_t)blockIdx.y * 128 + wm * 64 + i * 16 + g;
        size_t col  = (size_t)bxl * 128 + wn * 32 + tig * 2;
        if (out_half) {
            __half* C0 = (__half*)Cbase + blockIdx.z * sC + row0 * Nout + col;
            __half* C1 = C0 + 8 * (size_t)Nout;
#pragma unroll
            for (int j = 0; j < 4; j++) {
                *(__half2*)(C0 + j * 8) = __float22half2_rn(
                    make_float2(acc[i][j][0] * alpha, acc[i][j][1] * alpha));
                *(__half2*)(C1 + j * 8) = __float22half2_rn(
                    make_float2(acc[i][j][2] * alpha, acc[i][j][3] * alpha));
            }
        } else {
            float* C0 = (float*)Cbase + blockIdx.z * sC + row0 * Nout + col;
            float* C1 = C0 + 8 * (size_t)Nout;
#pragma unroll
            for (int j = 0; j < 4; j++) {
                *(float2*)(C0 + j * 8) =
                    make_float2(acc[i][j][0] * alpha, acc[i][j][1] * alpha);
                *(float2*)(C1 + j * 8) =
                    make_float2(acc[i][j][2] * alpha, acc[i][j][3] * alpha);
            }
        }
    }
}

// ---------------------------------------------------------------------------
// NN GEMM: C[M,N] = A[M,K] * B[K,N]  (half in, half out; B n-contiguous).
// B fragments via ldmatrix.trans. Same tiling/pipeline as NT.
// ---------------------------------------------------------------------------
#define LROWB 136                              // 128 + 8 pad halves
#define STG_NN (128 * LROWH + 64 * LROWB)      // 17920 halves
#define NN_SMEM (3 * STG_NN * 2)               // 107520 B

__global__ __launch_bounds__(256, 2)
void gemm_h_nn(const __half* __restrict__ Ag, const __half* __restrict__ Bg,
               __half* __restrict__ Cg, int M, int N, int K, int lda, int ldb,
               size_t sA, size_t sB, size_t sC)
{
    extern __shared__ __half sm[];
    const uint32_t sbase = smem_u32(sm);

    const int tid  = threadIdx.x;
    const int wid  = tid >> 5;
    const int lane = tid & 31;
    const int wm   = wid >> 2;
    const int wn   = wid & 3;
    const int g    = lane >> 2;
    const int tig  = lane & 3;
    const int l7 = lane & 7;
    const int t4 = lane >> 3;

    const __half* Ab = Ag + blockIdx.z * sA + (size_t)blockIdx.y * 128 * lda;
    const __half* Bb = Bg + blockIdx.z * sB + (size_t)blockIdx.x * 128;  // n offset

    float acc[4][4][4];
#pragma unroll
    for (int i = 0; i < 4; i++)
#pragma unroll
        for (int j = 0; j < 4; j++)
#pragma unroll
            for (int r = 0; r < 4; r++) acc[i][j][r] = 0.f;

    const int nk = K >> 6;

    auto load_stage = [&](int js) {
        uint32_t stH = (uint32_t)((js % 3) * STG_NN);
        const __half* ga = Ab + js * 64;
#pragma unroll
        for (int i = 0; i < 8; i++) {
            int c = tid + i * 256;
            if (i < 4) {
                int row = c >> 3;                 // 0..127
                int fh  = (c & 7) << 3;
                cp_async16(sbase + 2u * (stH + row * LROWH + fh),
                           ga + (size_t)row * lda + fh);
            } else {
                int cb  = c - 1024;
                int row = cb >> 4;                // 0..63 (k-rows)
                int fh  = (cb & 15) << 3;         // 0..120 (n)
                cp_async16(sbase + 2u * (stH + 128 * LROWH + row * LROWB + fh),
                           Bb + (size_t)(js * 64 + row) * ldb + fh);
            }
        }
        asm volatile("cp.async.commit_group;" ::: "memory");
    };

    load_stage(0);
    load_stage(1);

    const uint32_t aoff = (uint32_t)((wm * 64 + ((t4 & 1) << 3) + l7) * LROWH
                                     + ((t4 >> 1) << 3));
    // trans-B tiles: m0=(k,n) m1=(k+8,n) m2=(k,n+8) m3=(k+8,n+8)
    uint32_t boff[2];
#pragma unroll
    for (int jj = 0; jj < 2; jj++)
        boff[jj] = (uint32_t)((((t4 & 1) << 3) + l7) * LROWB
                              + wn * 32 + jj * 16 + ((t4 >> 1) << 3));

    for (int ks = 0; ks < nk; ks++) {
        asm volatile("cp.async.wait_group 1;" ::: "memory");
        __syncthreads();

        const uint32_t saA = sbase + 2u * (uint32_t)((ks % 3) * STG_NN);
        const uint32_t saB = saA + 2u * 128 * LROWH;

        uint32_t af[4][4], bf[2][4];
        auto ldfrag = [&](uint32_t kk) {
#pragma unroll
            for (int i = 0; i < 4; i++)
                ldsm_x4(af[i], saA + 2u * (aoff + i * 16 * LROWH + kk));
#pragma unroll
            for (int jj = 0; jj < 2; jj++)
                ldsm_x4_t(bf[jj], saB + 2u * (boff[jj] + kk * LROWB));
        };
        auto do_mma = [&]() {
#pragma unroll
            for (int i = 0; i < 4; i++)
#pragma unroll
                for (int j = 0; j < 4; j++)
                    mma_f16(acc[i][j], af[i], &bf[j >> 1][(j & 1) * 2]);
        };

        ldfrag(0);
        if (ks + 2 < nk) load_stage(ks + 2);
        else asm volatile("cp.async.commit_group;" ::: "memory");
        do_mma();
#pragma unroll
        for (int k16 = 1; k16 < 4; k16++) {
            ldfrag((uint32_t)(k16 * 16));
            do_mma();
        }
    }

#pragma unroll
    for (int i = 0; i < 4; i++) {
        size_t row0 = (size_t)blockIdx.y * 128 + wm * 64 + i * 16 + g;
        size_t col  = (size_t)blockIdx.x * 128 + wn * 32 + tig * 2;
        __half* C0 = Cg + blockIdx.z * sC + row0 * N + col;
        __half* C1 = C0 + 8 * (size_t)N;
#pragma unroll
        for (int j = 0; j < 4; j++) {
            *(__half2*)(C0 + j * 8) = __float22half2_rn(
                make_float2(acc[i][j][0], acc[i][j][1]));
            *(__half2*)(C1 + j * 8) = __float22half2_rn(
                make_float2(acc[i][j][2], acc[i][j][3]));
        }
    }
}

// ---------------------------------------------------------------------------
__global__ __launch_bounds__(256) void cvt_h_kernel(
    const float* __restrict__ in, __half* __restrict__ out, int n4)
{
    int i = blockIdx.x * blockDim.x + threadIdx.x;
    if (i < n4) {
        float4 v = ((const float4*)in)[i];
        __half2 lo = __float22half2_rn(make_float2(v.x, v.y));
        __half2 hi = __float22half2_rn(make_float2(v.z, v.w));
        *(uint2*)(out + 4 * (size_t)i) =
            make_uint2(*(uint32_t*)&lo, *(uint32_t*)&hi);
    }
}

__global__ __launch_bounds__(256) void cvt4_h_kernel(
    const float* __restrict__ w0, const float* __restrict__ w1,
    const float* __restrict__ w2, const float* __restrict__ w3,
    __half* __restrict__ out, int n4)
{
    int i = blockIdx.x * blockDim.x + threadIdx.x;
    if (i < 4 * n4) {
        int sel = i / n4, off = i - sel * n4;
        const float* src = (sel == 0) ? w0 : (sel == 1) ? w1 : (sel == 2) ? w2 : w3;
        float4 v = ((const float4*)src)[off];
        __half2 lo = __float22half2_rn(make_float2(v.x, v.y));
        __half2 hi = __float22half2_rn(make_float2(v.z, v.w));
        *(uint2*)(out + 4 * (size_t)i) =
            make_uint2(*(uint32_t*)&lo, *(uint32_t*)&hi);
    }
}

// ---------------------------------------------------------------------------
__global__ __launch_bounds__(256) void softmax_rows(
    const float* __restrict__ S, __half* __restrict__ P)
{
    const float* row = S + (size_t)blockIdx.x * TD;
    __half* prow = P + (size_t)blockIdx.x * TD;
    __shared__ float red[256];
    const int tid = threadIdx.x;

    float4 v0 = *(const float4*)(row + tid * 8);
    float4 v1 = *(const float4*)(row + tid * 8 + 4);
    float v[8] = {v0.x, v0.y, v0.z, v0.w, v1.x, v1.y, v1.z, v1.w};

    float m = -INFINITY;
#pragma unroll
    for (int i = 0; i < 8; i++) m = fmaxf(m, v[i]);
    red[tid] = m;
    __syncthreads();
    for (int s = 128; s > 0; s >>= 1) {
        if (tid < s) red[tid] = fmaxf(red[tid], red[tid + s]);
        __syncthreads();
    }
    m = red[0];
    __syncthreads();

    float sum = 0.f;
#pragma unroll
    for (int i = 0; i < 8; i++) {
        v[i] = __expf(v[i] - m);
        sum += v[i];
    }
    red[tid] = sum;
    __syncthreads();
    for (int s = 128; s > 0; s >>= 1) {
        if (tid < s) red[tid] += red[tid + s];
        __syncthreads();
    }
    float inv = 1.f / red[0];
    __half2 h[4];
#pragma unroll
    for (int i = 0; i < 4; i++)
        h[i] = __float22half2_rn(make_float2(v[2 * i] * inv, v[2 * i + 1] * inv));
    *(uint2*)(prow + tid * 8) =
        make_uint2(*(uint32_t*)&h[0], *(uint32_t*)&h[1]);
    *(uint2*)(prow + tid * 8 + 4) =
        make_uint2(*(uint32_t*)&h[2], *(uint32_t*)&h[3]);
}

// ---------------------------------------------------------------------------
extern "C" void kernel_launch(void* const* d_in, const int* in_sizes, int n_in,
                              void* d_out, int out_size)
{
    const float* x   = (const float*)d_in[0];
    const float* W_q = (const float*)d_in[1];
    const float* W_k = (const float*)d_in[2];
    const float* W_v = (const float*)d_in[3];
    const float* W_o = (const float*)d_in[4];
    float* out = (float*)d_out;

    __half* Xh;  cudaGetSymbolAddress((void**)&Xh,  g_Xh);
    __half* Wh;  cudaGetSymbolAddress((void**)&Wh,  g_Wh);
    __half* Qh;  cudaGetSymbolAddress((void**)&Qh,  g_Qh);
    __half* Kh;  cudaGetSymbolAddress((void**)&Kh,  g_Kh);
    __half* Vh;  cudaGetSymbolAddress((void**)&Vh,  g_Vh);
    float*  S;   cudaGetSymbolAddress((void**)&S,   g_S);
    __half* Ph;  cudaGetSymbolAddress((void**)&Ph,  g_Ph);
    __half* Ah;  cudaGetSymbolAddress((void**)&Ah,  g_Ah);

    cudaFuncSetAttribute(gemm_h, cudaFuncAttributeMaxDynamicSharedMemorySize, NT_SMEM);
    cudaFuncSetAttribute(gemm_h_nn, cudaFuncAttributeMaxDynamicSharedMemorySize, NN_SMEM);

    const int M = BD * TD;                        // 16384
    const float scale = 1.0f / sqrtf((float)TD);
    const size_t WN = (size_t)NHD * NXD;

    cvt_h_kernel<<<(M * NXD / 4 + 255) / 256, 256>>>(x, Xh, M * NXD / 4);
    cvt4_h_kernel<<<(int)(4 * (WN / 4) + 255) / 256, 256>>>(
        W_q, W_k, W_v, W_o, Wh, (int)(WN / 4));

    // One stacked launch: [Q|K|V] = Xh @ [Wq;Wk;Wv]^T, scattered to 3 buffers
    {
        dim3 g(NQKV / 128, M / 128, 1);
        gemm_h<<<g, 256, NT_SMEM>>>(Xh, Wh, nullptr, Qh, Kh, Vh, 1,
                                    M, NQKV, NXD, NXD, NXD, 1.f, 1, 0, 0, 0);
    }
    // S[b] = (Q_b @ K_b^T) / sqrt(T)   (f32; dedicated 2KB-stride operands)
    {
        dim3 g(TD / 128, TD / 128, BD);
        gemm_h<<<g, 256, NT_SMEM>>>(Qh, Kh, S, nullptr, nullptr, nullptr, 0,
                                    TD, TD, NHD, NHD, NHD, scale, 0,
                                    (size_t)TD * NHD, (size_t)TD * NHD,
                                    (size_t)TD * TD);
    }
    softmax_rows<<<BD * TD, 256>>>(S, Ph);

    // Ah[b] = Ph_b @ V_b   (NN: V n-contiguous, ldb=1024)
    {
        dim3 g(NHD / 128, TD / 128, BD);
        gemm_h_nn<<<g, 256, NN_SMEM>>>(Ph, Vh, Ah, TD, NHD, TD,
                                       TD, NHD,
                                       (size_t)TD * TD, (size_t)TD * NHD,
                                       (size_t)TD * NHD);
    }
    // out = Ah @ Wo^T   (f32)
    {
        dim3 g(NHD / 128, M / 128, 1);
        gemm_h<<<g, 256, NT_SMEM>>>(Ah, Wh + 3 * WN, out, nullptr, nullptr, nullptr, 0,
                                    M, NHD, NHD, NHD, NHD, 1.f, 0, 0, 0, 0);
    }
}

// round 13
// speedup vs baseline: 1.0597x; 1.0251x over previous
#include <cuda_runtime.h>
#include <cuda_fp16.h>
#include <math.h>
#include <stdint.h>

#define NXD 1024
#define NHD 1024
#define BD  8
#define TD  2048
#define NQKV 3072

// ---------------- scratch (device globals; allocation-free rule) ------------
__device__ __half g_Xh[BD * TD * NXD];               // 32 MiB
__device__ __half g_Wh[4u * NHD * NXD];              // 8 MiB (Wq,Wk,Wv,Wo stacked)
__device__ __half g_Qh[BD * TD * NHD];               // 32 MiB
__device__ __half g_Kh[BD * TD * NHD];               // 32 MiB
__device__ __half g_Vh[BD * TD * NHD];               // 32 MiB
__device__ __half g_Ph[(size_t)BD * TD * TD];        // 64 MiB (unnormalized exp)
__device__ float  g_sums[BD * TD];                   // row sums of exp
__device__ __half g_Ah[BD * TD * NHD];               // 32 MiB

// ---------------- helpers ----------------------------------------------
__device__ __forceinline__ uint32_t smem_u32(const void* p) {
    uint32_t a;
    asm("{ .reg .u64 t; cvta.to.shared.u64 t, %1; cvt.u32.u64 %0, t; }"
        : "=r"(a) : "l"(p));
    return a;
}
__device__ __forceinline__ void cp_async16(uint32_t dst, const void* src) {
    asm volatile("cp.async.cg.shared.global [%0], [%1], 16;"
                 :: "r"(dst), "l"(src) : "memory");
}
__device__ __forceinline__ void mma_f16(float c[4], const uint32_t a[4], const uint32_t b[2]) {
    asm volatile(
        "mma.sync.aligned.m16n8k16.row.col.f32.f16.f16.f32 "
        "{%0,%1,%2,%3}, {%4,%5,%6,%7}, {%8,%9}, {%0,%1,%2,%3};"
        : "+f"(c[0]), "+f"(c[1]), "+f"(c[2]), "+f"(c[3])
        : "r"(a[0]), "r"(a[1]), "r"(a[2]), "r"(a[3]),
          "r"(b[0]), "r"(b[1]));
}
__device__ __forceinline__ void ldsm_x4(uint32_t r[4], uint32_t addr) {
    asm volatile("ldmatrix.sync.aligned.m8n8.x4.shared.b16 {%0,%1,%2,%3}, [%4];"
                 : "=r"(r[0]), "=r"(r[1]), "=r"(r[2]), "=r"(r[3]) : "r"(addr));
}
__device__ __forceinline__ void ldsm_x4_t(uint32_t r[4], uint32_t addr) {
    asm volatile("ldmatrix.sync.aligned.m8n8.x4.trans.shared.b16 {%0,%1,%2,%3}, [%4];"
                 : "=r"(r[0]), "=r"(r[1]), "=r"(r[2]), "=r"(r[3]) : "r"(addr));
}

// ---------------------------------------------------------------------------
// NT GEMM: C[M,N] = alpha * A[M,K] * B[N,K]^T
// CTA 128x128, BK=64, warp tile 64x32, 3-stage cp.async, 2 CTAs/SM.
// Modes: split!=0 -> scatter columns to Cq/Ck/Cv (QKV).
//        do_exp!=0 -> C = half(exp(alpha*acc - 4)), atomicAdd row sums.
//        else out_half selects __half / float C.
// ---------------------------------------------------------------------------
#define LROWH 72
#define STG_NT ((128 + 128) * LROWH)
#define NT_SMEM (3 * STG_NT * 2)               // 110592 B

__global__ __launch_bounds__(256, 2)
void gemm_h(const __half* __restrict__ Ag, const __half* __restrict__ Bg,
            void* __restrict__ Cg,
            __half* __restrict__ Cq, __half* __restrict__ Ck,
            __half* __restrict__ Cv, int split,
            float* __restrict__ sums, int do_exp,
            int M, int N, int K, int lda, int ldb,
            float alpha, int out_half, size_t sA, size_t sB, size_t sC)
{
    extern __shared__ __half sm[];
    const uint32_t sbase = smem_u32(sm);

    const int tid  = threadIdx.x;
    const int wid  = tid >> 5;
    const int lane = tid & 31;
    const int wm   = wid >> 2;
    const int wn   = wid & 3;
    const int g    = lane >> 2;
    const int tig  = lane & 3;
    const int l7 = lane & 7;
    const int t4 = lane >> 3;

    const __half* Ab = Ag + blockIdx.z * sA + (size_t)blockIdx.y * 128 * lda;
    const __half* Bb = Bg + blockIdx.z * sB + (size_t)blockIdx.x * 128 * ldb;

    float acc[4][4][4];
#pragma unroll
    for (int i = 0; i < 4; i++)
#pragma unroll
        for (int j = 0; j < 4; j++)
#pragma unroll
            for (int r = 0; r < 4; r++) acc[i][j][r] = 0.f;

    const int nk = K >> 6;

    auto load_stage = [&](int js) {
        uint32_t stH = (uint32_t)((js % 3) * STG_NT);
        const __half* ga = Ab + js * 64;
        const __half* gb = Bb + js * 64;
#pragma unroll
        for (int i = 0; i < 8; i++) {
            int c   = tid + i * 256;
            int row = c >> 3;
            int fh  = (c & 7) << 3;
            uint32_t d = sbase + 2u * (stH + row * LROWH + fh);
            if (i < 4)  cp_async16(d, ga + (size_t)row * lda + fh);
            else        cp_async16(d, gb + (size_t)(row - 128) * ldb + fh);
        }
        asm volatile("cp.async.commit_group;" ::: "memory");
    };

    load_stage(0);
    load_stage(1);

    const uint32_t aoff = (uint32_t)((wm * 64 + ((t4 & 1) << 3) + l7) * LROWH
                                     + ((t4 >> 1) << 3));
    uint32_t boff[2];
#pragma unroll
    for (int jj = 0; jj < 2; jj++)
        boff[jj] = (uint32_t)((wn * 32 + jj * 16 + ((t4 >> 1) << 3) + l7) * LROWH
                              + ((t4 & 1) << 3));

    for (int ks = 0; ks < nk; ks++) {
        asm volatile("cp.async.wait_group 1;" ::: "memory");
        __syncthreads();

        const uint32_t saA = sbase + 2u * (uint32_t)((ks % 3) * STG_NT);
        const uint32_t saB = saA + 2u * 128 * LROWH;

        uint32_t af[4][4], bf[2][4];
        auto ldfrag = [&](uint32_t kk) {
#pragma unroll
            for (int i = 0; i < 4; i++)
                ldsm_x4(af[i], saA + 2u * (aoff + i * 16 * LROWH + kk));
#pragma unroll
            for (int jj = 0; jj < 2; jj++)
                ldsm_x4(bf[jj], saB + 2u * (boff[jj] + kk));
        };
        auto do_mma = [&]() {
#pragma unroll
            for (int i = 0; i < 4; i++)
#pragma unroll
                for (int j = 0; j < 4; j++)
                    mma_f16(acc[i][j], af[i], &bf[j >> 1][(j & 1) * 2]);
        };

        ldfrag(0);
        if (ks + 2 < nk) load_stage(ks + 2);
        else asm volatile("cp.async.commit_group;" ::: "memory");
        do_mma();
#pragma unroll
        for (int k16 = 1; k16 < 4; k16++) {
            ldfrag((uint32_t)(k16 * 16));
            do_mma();
        }
    }

    if (do_exp) {
        // C = half(exp(alpha*acc - 4)); row sums -> atomicAdd(sums).
        float* srow = sums + blockIdx.z * TD;
#pragma unroll
        for (int i = 0; i < 4; i++) {
            size_t row0 = (size_t)blockIdx.y * 128 + wm * 64 + i * 16 + g;
            size_t col  = (size_t)blockIdx.x * 128 + wn * 32 + tig * 2;
            __half* C0 = (__half*)Cg + blockIdx.z * sC + row0 * N + col;
            __half* C1 = C0 + 8 * (size_t)N;
            float ev[4][4];
#pragma unroll
            for (int j = 0; j < 4; j++)
#pragma unroll
                for (int r = 0; r < 4; r++)
                    ev[j][r] = __expf(acc[i][j][r] * alpha - 4.0f);
            float p0 = 0.f, p1 = 0.f;
#pragma unroll
            for (int j = 0; j < 4; j++) {
                __half2 h0 = __float22half2_rn(make_float2(ev[j][0], ev[j][1]));
                __half2 h1 = __float22half2_rn(make_float2(ev[j][2], ev[j][3]));
                *(__half2*)(C0 + j * 8) = h0;
                *(__half2*)(C1 + j * 8) = h1;
                // Sum the half-rounded values so denominators match numerators.
                float2 f0 = __half22float2(h0), f1 = __half22float2(h1);
                p0 += f0.x + f0.y;
                p1 += f1.x + f1.y;
            }
            p0 += __shfl_xor_sync(0xffffffffu, p0, 1);
            p0 += __shfl_xor_sync(0xffffffffu, p0, 2);
            p1 += __shfl_xor_sync(0xffffffffu, p1, 1);
            p1 += __shfl_xor_sync(0xffffffffu, p1, 2);
            if (tig == 0) {
                atomicAdd(&srow[row0], p0);
                atomicAdd(&srow[row0 + 8], p1);
            }
        }
        return;
    }

    // Standard epilogue
    int  Nout = N;
    int  bxl  = blockIdx.x;
    void* Cbase = Cg;
    if (split) {
        int sel = blockIdx.x >> 3;
        bxl = blockIdx.x & 7;
        Nout = NHD;
        Cbase = (sel == 0) ? (void*)Cq : (sel == 1) ? (void*)Ck : (void*)Cv;
    }
#pragma unroll
    for (int i = 0; i < 4; i++) {
        size_t row0 = (size_t)blockIdx.y * 128 + wm * 64 + i * 16 + g;
        size_t col  = (size_t)bxl * 128 + wn * 32 + tig * 2;
        if (out_half) {
            __half* C0 = (__half*)Cbase + blockIdx.z * sC + row0 * Nout + col;
            __half* C1 = C0 + 8 * (size_t)Nout;
#pragma unroll
            for (int j = 0; j < 4; j++) {
                *(__half2*)(C0 + j * 8) = __float22half2_rn(
                    make_float2(acc[i][j][0] * alpha, acc[i][j][1] * alpha));
                *(__half2*)(C1 + j * 8) = __float22half2_rn(
                    make_float2(acc[i][j][2] * alpha, acc[i][j][3] * alpha));
            }
        } else {
            float* C0 = (float*)Cbase + blockIdx.z * sC + row0 * Nout + col;
            float* C1 = C0 + 8 * (size_t)Nout;
#pragma unroll
            for (int j = 0; j < 4; j++) {
                *(float2*)(C0 + j * 8) =
                    make_float2(acc[i][j][0] * alpha, acc[i][j][1] * alpha);
                *(float2*)(C1 + j * 8) =
                    make_float2(acc[i][j][2] * alpha, acc[i][j][3] * alpha);
            }
        }
    }
}

// ---------------------------------------------------------------------------
// NN GEMM: C[M,N] = rowscale(A[M,K] * B[K,N])  (half; B n-contiguous)
// rowscale: C row r multiplied by 1/sums[r] (softmax normalization).
// ---------------------------------------------------------------------------
#define LROWB 136
#define STG_NN (128 * LROWH + 64 * LROWB)
#define NN_SMEM (3 * STG_NN * 2)               // 107520 B

__global__ __launch_bounds__(256, 2)
void gemm_h_nn(const __half* __restrict__ Ag, const __half* __restrict__ Bg,
               __half* __restrict__ Cg, const float* __restrict__ sums,
               int M, int N, int K, int lda, int ldb,
               size_t sA, size_t sB, size_t sC)
{
    extern __shared__ __half sm[];
    const uint32_t sbase = smem_u32(sm);

    const int tid  = threadIdx.x;
    const int wid  = tid >> 5;
    const int lane = tid & 31;
    const int wm   = wid >> 2;
    const int wn   = wid & 3;
    const int g    = lane >> 2;
    const int tig  = lane & 3;
    const int l7 = lane & 7;
    const int t4 = lane >> 3;

    const __half* Ab = Ag + blockIdx.z * sA + (size_t)blockIdx.y * 128 * lda;
    const __half* Bb = Bg + blockIdx.z * sB + (size_t)blockIdx.x * 128;

    float acc[4][4][4];
#pragma unroll
    for (int i = 0; i < 4; i++)
#pragma unroll
        for (int j = 0; j < 4; j++)
#pragma unroll
            for (int r = 0; r < 4; r++) acc[i][j][r] = 0.f;

    const int nk = K >> 6;

    auto load_stage = [&](int js) {
        uint32_t stH = (uint32_t)((js % 3) * STG_NN);
        const __half* ga = Ab + js * 64;
#pragma unroll
        for (int i = 0; i < 8; i++) {
            int c = tid + i * 256;
            if (i < 4) {
                int row = c >> 3;
                int fh  = (c & 7) << 3;
                cp_async16(sbase + 2u * (stH + row * LROWH + fh),
                           ga + (size_t)row * lda + fh);
            } else {
                int cb  = c - 1024;
                int row = cb >> 4;
                int fh  = (cb & 15) << 3;
                cp_async16(sbase + 2u * (stH + 128 * LROWH + row * LROWB + fh),
                           Bb + (size_t)(js * 64 + row) * ldb + fh);
            }
        }
        asm volatile("cp.async.commit_group;" ::: "memory");
    };

    load_stage(0);
    load_stage(1);

    const uint32_t aoff = (uint32_t)((wm * 64 + ((t4 & 1) << 3) + l7) * LROWH
                                     + ((t4 >> 1) << 3));
    uint32_t boff[2];
#pragma unroll
    for (int jj = 0; jj < 2; jj++)
        boff[jj] = (uint32_t)((((t4 & 1) << 3) + l7) * LROWB
                              + wn * 32 + jj * 16 + ((t4 >> 1) << 3));

    for (int ks = 0; ks < nk; ks++) {
        asm volatile("cp.async.wait_group 1;" ::: "memory");
        __syncthreads();

        const uint32_t saA = sbase + 2u * (uint32_t)((ks % 3) * STG_NN);
        const uint32_t saB = saA + 2u * 128 * LROWH;

        uint32_t af[4][4], bf[2][4];
        auto ldfrag = [&](uint32_t kk) {
#pragma unroll
            for (int i = 0; i < 4; i++)
                ldsm_x4(af[i], saA + 2u * (aoff + i * 16 * LROWH + kk));
#pragma unroll
            for (int jj = 0; jj < 2; jj++)
                ldsm_x4_t(bf[jj], saB + 2u * (boff[jj] + kk * LROWB));
        };
        auto do_mma = [&]() {
#pragma unroll
            for (int i = 0; i < 4; i++)
#pragma unroll
                for (int j = 0; j < 4; j++)
                    mma_f16(acc[i][j], af[i], &bf[j >> 1][(j & 1) * 2]);
        };

        ldfrag(0);
        if (ks + 2 < nk) load_stage(ks + 2);
        else asm volatile("cp.async.commit_group;" ::: "memory");
        do_mma();
#pragma unroll
        for (int k16 = 1; k16 < 4; k16++) {
            ldfrag((uint32_t)(k16 * 16));
            do_mma();
        }
    }

    const float* srow = sums + blockIdx.z * TD;
#pragma unroll
    for (int i = 0; i < 4; i++) {
        size_t row0 = (size_t)blockIdx.y * 128 + wm * 64 + i * 16 + g;
        size_t col  = (size_t)blockIdx.x * 128 + wn * 32 + tig * 2;
        float inv0 = 1.0f / __ldg(&srow[row0]);
        float inv1 = 1.0f / __ldg(&srow[row0 + 8]);
        __half* C0 = Cg + blockIdx.z * sC + row0 * N + col;
        __half* C1 = C0 + 8 * (size_t)N;
#pragma unroll
        for (int j = 0; j < 4; j++) {
            *(__half2*)(C0 + j * 8) = __float22half2_rn(
                make_float2(acc[i][j][0] * inv0, acc[i][j][1] * inv0));
            *(__half2*)(C1 + j * 8) = __float22half2_rn(
                make_float2(acc[i][j][2] * inv1, acc[i][j][3] * inv1));
        }
    }
}

// ---------------------------------------------------------------------------
__global__ __launch_bounds__(256) void cvt_h_kernel(
    const float* __restrict__ in, __half* __restrict__ out, int n4)
{
    int i = blockIdx.x * blockDim.x + threadIdx.x;
    if (i < n4) {
        float4 v = ((const float4*)in)[i];
        __half2 lo = __float22half2_rn(make_float2(v.x, v.y));
        __half2 hi = __float22half2_rn(make_float2(v.z, v.w));
        *(uint2*)(out + 4 * (size_t)i) =
            make_uint2(*(uint32_t*)&lo, *(uint32_t*)&hi);
    }
}

__global__ __launch_bounds__(256) void cvt4_h_kernel(
    const float* __restrict__ w0, const float* __restrict__ w1,
    const float* __restrict__ w2, const float* __restrict__ w3,
    __half* __restrict__ out, int n4)
{
    int i = blockIdx.x * blockDim.x + threadIdx.x;
    if (i < 4 * n4) {
        int sel = i / n4, off = i - sel * n4;
        const float* src = (sel == 0) ? w0 : (sel == 1) ? w1 : (sel == 2) ? w2 : w3;
        float4 v = ((const float4*)src)[off];
        __half2 lo = __float22half2_rn(make_float2(v.x, v.y));
        __half2 hi = __float22half2_rn(make_float2(v.z, v.w));
        *(uint2*)(out + 4 * (size_t)i) =
            make_uint2(*(uint32_t*)&lo, *(uint32_t*)&hi);
    }
}

// ---------------------------------------------------------------------------
extern "C" void kernel_launch(void* const* d_in, const int* in_sizes, int n_in,
                              void* d_out, int out_size)
{
    const float* x   = (const float*)d_in[0];
    const float* W_q = (const float*)d_in[1];
    const float* W_k = (const float*)d_in[2];
    const float* W_v = (const float*)d_in[3];
    const float* W_o = (const float*)d_in[4];
    float* out = (float*)d_out;

    __half* Xh;  cudaGetSymbolAddress((void**)&Xh,  g_Xh);
    __half* Wh;  cudaGetSymbolAddress((void**)&Wh,  g_Wh);
    __half* Qh;  cudaGetSymbolAddress((void**)&Qh,  g_Qh);
    __half* Kh;  cudaGetSymbolAddress((void**)&Kh,  g_Kh);
    __half* Vh;  cudaGetSymbolAddress((void**)&Vh,  g_Vh);
    __half* Ph;  cudaGetSymbolAddress((void**)&Ph,  g_Ph);
    float*  Sm;  cudaGetSymbolAddress((void**)&Sm,  g_sums);
    __half* Ah;  cudaGetSymbolAddress((void**)&Ah,  g_Ah);

    cudaFuncSetAttribute(gemm_h, cudaFuncAttributeMaxDynamicSharedMemorySize, NT_SMEM);
    cudaFuncSetAttribute(gemm_h_nn, cudaFuncAttributeMaxDynamicSharedMemorySize, NN_SMEM);

    const int M = BD * TD;                        // 16384
    const float scale = 1.0f / sqrtf((float)TD);
    const size_t WN = (size_t)NHD * NXD;
    const size_t TT = (size_t)TD * TD;
    const size_t TN = (size_t)TD * NHD;

    // Zero row-sum accumulators (per replay; graph-capturable).
    cudaMemsetAsync(Sm, 0, BD * TD * sizeof(float));

    cvt_h_kernel<<<(M * NXD / 4 + 255) / 256, 256>>>(x, Xh, M * NXD / 4);
    cvt4_h_kernel<<<(int)(4 * (WN / 4) + 255) / 256, 256>>>(
        W_q, W_k, W_v, W_o, Wh, (int)(WN / 4));

    // QKV (stacked launch, scatter epilogue)
    {
        dim3 g(NQKV / 128, M / 128, 1);
        gemm_h<<<g, 256, NT_SMEM>>>(Xh, Wh, nullptr, Qh, Kh, Vh, 1,
                                    nullptr, 0,
                                    M, NQKV, NXD, NXD, NXD, 1.f, 1, 0, 0, 0);
    }
    // P[b] = exp(Q_b K_b^T / sqrt(T) - 4)  (half) + row sums via atomics
    {
        dim3 g(TD / 128, TD / 128, BD);
        gemm_h<<<g, 256, NT_SMEM>>>(Qh, Kh, Ph, nullptr, nullptr, nullptr, 0,
                                    Sm, 1,
                                    TD, TD, NHD, NHD, NHD, scale, 1,
                                    TN, TN, TT);
    }
    // Ah[b] = (P_b @ V_b) / rowsums  (softmax normalization folded in)
    {
        dim3 g(NHD / 128, TD / 128, BD);
        gemm_h_nn<<<g, 256, NN_SMEM>>>(Ph, Vh, Ah, Sm,
                                       TD, NHD, TD, TD, NHD,
                                       TT, TN, TN);
    }
    // out = Ah @ Wo^T   (f32)
    {
        dim3 g(NHD / 128, M / 128, 1);
        gemm_h<<<g, 256, NT_SMEM>>>(Ah, Wh + 3 * WN, out,
                                    nullptr, nullptr, nullptr, 0,
                                    nullptr, 0,
                                    M, NHD, NHD, NHD, NHD, 1.f, 0, 0, 0, 0);
    }
}

// round 15
// speedup vs baseline: 1.2061x; 1.1382x over previous
#include <cuda_runtime.h>
#include <cuda_fp16.h>
#include <math.h>
#include <stdint.h>

#define NXD 1024
#define NHD 1024
#define BD  8
#define TD  2048
#define NQKV 3072

// ---------------- scratch (device globals; allocation-free rule) ------------
__device__ __half g_Xh[BD * TD * NXD];               // 32 MiB
__device__ __half g_Wh[4u * NHD * NXD];              // 8 MiB (Wq,Wk,Wv,Wo)
__device__ __half g_Wvo[(size_t)NHD * NXD];          // 2 MiB (Wo @ Wv)
__device__ __half g_Qh[BD * TD * NHD];               // 32 MiB
__device__ __half g_Kh[BD * TD * NHD];               // 32 MiB
__device__ __half g_Vh[BD * TD * NHD];               // 32 MiB (holds V' = x @ Wvo^T)
__device__ __half g_Ph[(size_t)BD * TD * TD];        // 64 MiB (unnormalized exp)
__device__ float  g_sums[BD * TD];                   // row sums of exp

// ---------------- helpers ----------------------------------------------
__device__ __forceinline__ uint32_t smem_u32(const void* p) {
    uint32_t a;
    asm("{ .reg .u64 t; cvta.to.shared.u64 t, %1; cvt.u32.u64 %0, t; }"
        : "=r"(a) : "l"(p));
    return a;
}
__device__ __forceinline__ void cp_async16(uint32_t dst, const void* src) {
    asm volatile("cp.async.cg.shared.global [%0], [%1], 16;"
                 :: "r"(dst), "l"(src) : "memory");
}
__device__ __forceinline__ void mma_f16(float c[4], const uint32_t a[4], const uint32_t b[2]) {
    asm volatile(
        "mma.sync.aligned.m16n8k16.row.col.f32.f16.f16.f32 "
        "{%0,%1,%2,%3}, {%4,%5,%6,%7}, {%8,%9}, {%0,%1,%2,%3};"
        : "+f"(c[0]), "+f"(c[1]), "+f"(c[2]), "+f"(c[3])
        : "r"(a[0]), "r"(a[1]), "r"(a[2]), "r"(a[3]),
          "r"(b[0]), "r"(b[1]));
}
__device__ __forceinline__ void ldsm_x4(uint32_t r[4], uint32_t addr) {
    asm volatile("ldmatrix.sync.aligned.m8n8.x4.shared.b16 {%0,%1,%2,%3}, [%4];"
                 : "=r"(r[0]), "=r"(r[1]), "=r"(r[2]), "=r"(r[3]) : "r"(addr));
}
__device__ __forceinline__ void ldsm_x4_t(uint32_t r[4], uint32_t addr) {
    asm volatile("ldmatrix.sync.aligned.m8n8.x4.trans.shared.b16 {%0,%1,%2,%3}, [%4];"
                 : "=r"(r[0]), "=r"(r[1]), "=r"(r[2]), "=r"(r[3]) : "r"(addr));
}

// ---------------------------------------------------------------------------
// NT GEMM: C[M,N] = alpha * A[M,K] * B[N,K]^T
// CTA 128x128, BK=64, warp tile 64x32, 3-stage cp.async, 2 CTAs/SM.
// Modes: split!=0 -> scatter columns to Cq/Ck/Cv; col tiles >=16 read Bg2.
//        do_exp!=0 -> C = half(exp(alpha*acc - 4)), atomicAdd row sums.
// ---------------------------------------------------------------------------
#define LROWH 72
#define STG_NT ((128 + 128) * LROWH)
#define NT_SMEM (3 * STG_NT * 2)               // 110592 B

__global__ __launch_bounds__(256, 2)
void gemm_h(const __half* __restrict__ Ag, const __half* __restrict__ Bg,
            const __half* __restrict__ Bg2,
            void* __restrict__ Cg,
            __half* __restrict__ Cq, __half* __restrict__ Ck,
            __half* __restrict__ Cv, int split,
            float* __restrict__ sums, int do_exp,
            int M, int N, int K, int lda, int ldb,
            float alpha, size_t sA, size_t sB, size_t sC)
{
    extern __shared__ __half sm[];
    const uint32_t sbase = smem_u32(sm);

    const int tid  = threadIdx.x;
    const int wid  = tid >> 5;
    const int lane = tid & 31;
    const int wm   = wid >> 2;
    const int wn   = wid & 3;
    const int g    = lane >> 2;
    const int tig  = lane & 3;
    const int l7 = lane & 7;
    const int t4 = lane >> 3;

    const __half* Ab = Ag + blockIdx.z * sA + (size_t)blockIdx.y * 128 * lda;
    const __half* Bb;
    if (split && blockIdx.x >= 16)
        Bb = Bg2 + (size_t)(blockIdx.x - 16) * 128 * ldb;
    else
        Bb = Bg + blockIdx.z * sB + (size_t)blockIdx.x * 128 * ldb;

    float acc[4][4][4];
#pragma unroll
    for (int i = 0; i < 4; i++)
#pragma unroll
        for (int j = 0; j < 4; j++)
#pragma unroll
            for (int r = 0; r < 4; r++) acc[i][j][r] = 0.f;

    const int nk = K >> 6;

    auto load_stage = [&](int js) {
        uint32_t stH = (uint32_t)((js % 3) * STG_NT);
        const __half* ga = Ab + js * 64;
        const __half* gb = Bb + js * 64;
#pragma unroll
        for (int i = 0; i < 8; i++) {
            int c   = tid + i * 256;
            int row = c >> 3;
            int fh  = (c & 7) << 3;
            uint32_t d = sbase + 2u * (stH + row * LROWH + fh);
            if (i < 4)  cp_async16(d, ga + (size_t)row * lda + fh);
            else        cp_async16(d, gb + (size_t)(row - 128) * ldb + fh);
        }
        asm volatile("cp.async.commit_group;" ::: "memory");
    };

    load_stage(0);
    load_stage(1);

    const uint32_t aoff = (uint32_t)((wm * 64 + ((t4 & 1) << 3) + l7) * LROWH
                                     + ((t4 >> 1) << 3));
    uint32_t boff[2];
#pragma unroll
    for (int jj = 0; jj < 2; jj++)
        boff[jj] = (uint32_t)((wn * 32 + jj * 16 + ((t4 >> 1) << 3) + l7) * LROWH
                              + ((t4 & 1) << 3));

    for (int ks = 0; ks < nk; ks++) {
        asm volatile("cp.async.wait_group 1;" ::: "memory");
        __syncthreads();

        const uint32_t saA = sbase + 2u * (uint32_t)((ks % 3) * STG_NT);
        const uint32_t saB = saA + 2u * 128 * LROWH;

        uint32_t af[4][4], bf[2][4];
        auto ldfrag = [&](uint32_t kk) {
#pragma unroll
            for (int i = 0; i < 4; i++)
                ldsm_x4(af[i], saA + 2u * (aoff + i * 16 * LROWH + kk));
#pragma unroll
            for (int jj = 0; jj < 2; jj++)
                ldsm_x4(bf[jj], saB + 2u * (boff[jj] + kk));
        };
        auto do_mma = [&]() {
#pragma unroll
            for (int i = 0; i < 4; i++)
#pragma unroll
                for (int j = 0; j < 4; j++)
                    mma_f16(acc[i][j], af[i], &bf[j >> 1][(j & 1) * 2]);
        };

        ldfrag(0);
        if (ks + 2 < nk) load_stage(ks + 2);
        else asm volatile("cp.async.commit_group;" ::: "memory");
        do_mma();
#pragma unroll
        for (int k16 = 1; k16 < 4; k16++) {
            ldfrag((uint32_t)(k16 * 16));
            do_mma();
        }
    }

    if (do_exp) {
        // C = half(exp(alpha*acc - 4)); row sums -> atomicAdd(sums).
        float* srow = sums + blockIdx.z * TD;
#pragma unroll
        for (int i = 0; i < 4; i++) {
            size_t row0 = (size_t)blockIdx.y * 128 + wm * 64 + i * 16 + g;
            size_t col  = (size_t)blockIdx.x * 128 + wn * 32 + tig * 2;
            __half* C0 = (__half*)Cg + blockIdx.z * sC + row0 * N + col;
            __half* C1 = C0 + 8 * (size_t)N;
            float ev[4][4];
#pragma unroll
            for (int j = 0; j < 4; j++)
#pragma unroll
                for (int r = 0; r < 4; r++)
                    ev[j][r] = __expf(acc[i][j][r] * alpha - 4.0f);
            float p0 = 0.f, p1 = 0.f;
#pragma unroll
            for (int j = 0; j < 4; j++) {
                __half2 h0 = __float22half2_rn(make_float2(ev[j][0], ev[j][1]));
                __half2 h1 = __float22half2_rn(make_float2(ev[j][2], ev[j][3]));
                *(__half2*)(C0 + j * 8) = h0;
                *(__half2*)(C1 + j * 8) = h1;
                float2 f0 = __half22float2(h0), f1 = __half22float2(h1);
                p0 += f0.x + f0.y;
                p1 += f1.x + f1.y;
            }
            p0 += __shfl_xor_sync(0xffffffffu, p0, 1);
            p0 += __shfl_xor_sync(0xffffffffu, p0, 2);
            p1 += __shfl_xor_sync(0xffffffffu, p1, 1);
            p1 += __shfl_xor_sync(0xffffffffu, p1, 2);
            if (tig == 0) {
                atomicAdd(&srow[row0], p0);
                atomicAdd(&srow[row0 + 8], p1);
            }
        }
        return;
    }

    // half epilogue (QKV scatter or plain half C)
    int  Nout = N;
    int  bxl  = blockIdx.x;
    void* Cbase = Cg;
    if (split) {
        int sel = blockIdx.x >> 3;
        bxl = blockIdx.x & 7;
        Nout = NHD;
        Cbase = (sel == 0) ? (void*)Cq : (sel == 1) ? (void*)Ck : (void*)Cv;
    }
#pragma unroll
    for (int i = 0; i < 4; i++) {
        size_t row0 = (size_t)blockIdx.y * 128 + wm * 64 + i * 16 + g;
        size_t col  = (size_t)bxl * 128 + wn * 32 + tig * 2;
        __half* C0 = (__half*)Cbase + blockIdx.z * sC + row0 * Nout + col;
        __half* C1 = C0 + 8 * (size_t)Nout;
#pragma unroll
        for (int j = 0; j < 4; j++) {
            *(__half2*)(C0 + j * 8) = __float22half2_rn(
                make_float2(acc[i][j][0] * alpha, acc[i][j][1] * alpha));
            *(__half2*)(C1 + j * 8) = __float22half2_rn(
                make_float2(acc[i][j][2] * alpha, acc[i][j][3] * alpha));
        }
    }
}

// ---------------------------------------------------------------------------
// NN GEMM: C[M,N] = rowscale(A[M,K] * B[K,N])  (half in; B n-contiguous)
// sums!=nullptr: row r scaled by 1/sums[r]. out_f32: float C else half C.
// ---------------------------------------------------------------------------
#define LROWB 136
#define STG_NN (128 * LROWH + 64 * LROWB)
#define NN_SMEM (3 * STG_NN * 2)               // 107520 B

__global__ __launch_bounds__(256, 2)
void gemm_h_nn(const __half* __restrict__ Ag, const __half* __restrict__ Bg,
               void* __restrict__ Cg, const float* __restrict__ sums,
               int out_f32,
               int M, int N, int K, int lda, int ldb,
               size_t sA, size_t sB, size_t sC)
{
    extern __shared__ __half sm[];
    const uint32_t sbase = smem_u32(sm);

    const int tid  = threadIdx.x;
    const int wid  = tid >> 5;
    const int lane = tid & 31;
    const int wm   = wid >> 2;
    const int wn   = wid & 3;
    const int g    = lane >> 2;
    const int tig  = lane & 3;
    const int l7 = lane & 7;
    const int t4 = lane >> 3;

    const __half* Ab = Ag + blockIdx.z * sA + (size_t)blockIdx.y * 128 * lda;
    const __half* Bb = Bg + blockIdx.z * sB + (size_t)blockIdx.x * 128;

    float acc[4][4][4];
#pragma unroll
    for (int i = 0; i < 4; i++)
#pragma unroll
        for (int j = 0; j < 4; j++)
#pragma unroll
            for (int r = 0; r < 4; r++) acc[i][j][r] = 0.f;

    const int nk = K >> 6;

    auto load_stage = [&](int js) {
        uint32_t stH = (uint32_t)((js % 3) * STG_NN);
        const __half* ga = Ab + js * 64;
#pragma unroll
        for (int i = 0; i < 8; i++) {
            int c = tid + i * 256;
            if (i < 4) {
                int row = c >> 3;
                int fh  = (c & 7) << 3;
                cp_async16(sbase + 2u * (stH + row * LROWH + fh),
                           ga + (size_t)row * lda + fh);
            } else {
                int cb  = c - 1024;
                int row = cb >> 4;
                int fh  = (cb & 15) << 3;
                cp_async16(sbase + 2u * (stH + 128 * LROWH + row * LROWB + fh),
                           Bb + (size_t)(js * 64 + row) * ldb + fh);
            }
        }
        asm volatile("cp.async.commit_group;" ::: "memory");
    };

    load_stage(0);
    load_stage(1);

    const uint32_t aoff = (uint32_t)((wm * 64 + ((t4 & 1) << 3) + l7) * LROWH
                                     + ((t4 >> 1) << 3));
    uint32_t boff[2];
#pragma unroll
    for (int jj = 0; jj < 2; jj++)
        boff[jj] = (uint32_t)((((t4 & 1) << 3) + l7) * LROWB
                              + wn * 32 + jj * 16 + ((t4 >> 1) << 3));

    for (int ks = 0; ks < nk; ks++) {
        asm volatile("cp.async.wait_group 1;" ::: "memory");
        __syncthreads();

        const uint32_t saA = sbase + 2u * (uint32_t)((ks % 3) * STG_NN);
        const uint32_t saB = saA + 2u * 128 * LROWH;

        uint32_t af[4][4], bf[2][4];
        auto ldfrag = [&](uint32_t kk) {
#pragma unroll
            for (int i = 0; i < 4; i++)
                ldsm_x4(af[i], saA + 2u * (aoff + i * 16 * LROWH + kk));
#pragma unroll
            for (int jj = 0; jj < 2; jj++)
                ldsm_x4_t(bf[jj], saB + 2u * (boff[jj] + kk * LROWB));
        };
        auto do_mma = [&]() {
#pragma unroll
            for (int i = 0; i < 4; i++)
#pragma unroll
                for (int j = 0; j < 4; j++)
                    mma_f16(acc[i][j], af[i], &bf[j >> 1][(j & 1) * 2]);
        };

        ldfrag(0);
        if (ks + 2 < nk) load_stage(ks + 2);
        else asm volatile("cp.async.commit_group;" ::: "memory");
        do_mma();
#pragma unroll
        for (int k16 = 1; k16 < 4; k16++) {
            ldfrag((uint32_t)(k16 * 16));
            do_mma();
        }
    }

    const float* srow = sums ? sums + blockIdx.z * TD : nullptr;
#pragma unroll
    for (int i = 0; i < 4; i++) {
        size_t row0 = (size_t)blockIdx.y * 128 + wm * 64 + i * 16 + g;
        size_t col  = (size_t)blockIdx.x * 128 + wn * 32 + tig * 2;
        float inv0 = srow ? (1.0f / __ldg(&srow[row0]))     : 1.0f;
        float inv1 = srow ? (1.0f / __ldg(&srow[row0 + 8])) : 1.0f;
        if (out_f32) {
            float* C0 = (float*)Cg + blockIdx.z * sC + row0 * N + col;
            float* C1 = C0 + 8 * (size_t)N;
#pragma unroll
            for (int j = 0; j < 4; j++) {
                *(float2*)(C0 + j * 8) =
                    make_float2(acc[i][j][0] * inv0, acc[i][j][1] * inv0);
                *(float2*)(C1 + j * 8) =
                    make_float2(acc[i][j][2] * inv1, acc[i][j][3] * inv1);
            }
        } else {
            __half* C0 = (__half*)Cg + blockIdx.z * sC + row0 * N + col;
            __half* C1 = C0 + 8 * (size_t)N;
#pragma unroll
            for (int j = 0; j < 4; j++) {
                *(__half2*)(C0 + j * 8) = __float22half2_rn(
                    make_float2(acc[i][j][0] * inv0, acc[i][j][1] * inv0));
                *(__half2*)(C1 + j * 8) = __float22half2_rn(
                    make_float2(acc[i][j][2] * inv1, acc[i][j][3] * inv1));
            }
        }
    }
}

// ---------------------------------------------------------------------------
__global__ __launch_bounds__(256) void cvt_h_kernel(
    const float* __restrict__ in, __half* __restrict__ out, int n4)
{
    int i = blockIdx.x * blockDim.x + threadIdx.x;
    if (i < n4) {
        float4 v = ((const float4*)in)[i];
        __half2 lo = __float22half2_rn(make_float2(v.x, v.y));
        __half2 hi = __float22half2_rn(make_float2(v.z, v.w));
        *(uint2*)(out + 4 * (size_t)i) =
            make_uint2(*(uint32_t*)&lo, *(uint32_t*)&hi);
    }
}

__global__ __launch_bounds__(256) void cvt4_h_kernel(
    const float* __restrict__ w0, const float* __restrict__ w1,
    const float* __restrict__ w2, const float* __restrict__ w3,
    __half* __restrict__ out, int n4)
{
    int i = blockIdx.x * blockDim.x + threadIdx.x;
    if (i < 4 * n4) {
        int sel = i / n4, off = i - sel * n4;
        const float* src = (sel == 0) ? w0 : (sel == 1) ? w1 : (sel == 2) ? w2 : w3;
        float4 v = ((const float4*)src)[off];
        __half2 lo = __float22half2_rn(make_float2(v.x, v.y));
        __half2 hi = __float22half2_rn(make_float2(v.z, v.w));
        *(uint2*)(out + 4 * (size_t)i) =
            make_uint2(*(uint32_t*)&lo, *(uint32_t*)&hi);
    }
}

// ---------------------------------------------------------------------------
extern "C" void kernel_launch(void* const* d_in, const int* in_sizes, int n_in,
                              void* d_out, int out_size)
{
    const float* x   = (const float*)d_in[0];
    const float* W_q = (const float*)d_in[1];
    const float* W_k = (const float*)d_in[2];
    const float* W_v = (const float*)d_in[3];
    const float* W_o = (const float*)d_in[4];
    float* out = (float*)d_out;

    __half* Xh;  cudaGetSymbolAddress((void**)&Xh,  g_Xh);
    __half* Wh;  cudaGetSymbolAddress((void**)&Wh,  g_Wh);
    __half* Wvo; cudaGetSymbolAddress((void**)&Wvo, g_Wvo);
    __half* Qh;  cudaGetSymbolAddress((void**)&Qh,  g_Qh);
    __half* Kh;  cudaGetSymbolAddress((void**)&Kh,  g_Kh);
    __half* Vh;  cudaGetSymbolAddress((void**)&Vh,  g_Vh);
    __half* Ph;  cudaGetSymbolAddress((void**)&Ph,  g_Ph);
    float*  Sm;  cudaGetSymbolAddress((void**)&Sm,  g_sums);

    cudaFuncSetAttribute(gemm_h, cudaFuncAttributeMaxDynamicSharedMemorySize, NT_SMEM);
    cudaFuncSetAttribute(gemm_h_nn, cudaFuncAttributeMaxDynamicSharedMemorySize, NN_SMEM);

    const int M = BD * TD;                        // 16384
    const float scale = 1.0f / sqrtf((float)TD);
    const size_t WN = (size_t)NHD * NXD;
    const size_t TT = (size_t)TD * TD;
    const size_t TN = (size_t)TD * NHD;

    // Zero row-sum accumulators (per replay; graph-capturable).
    cudaMemsetAsync(Sm, 0, BD * TD * sizeof(float));

    cvt_h_kernel<<<(M * NXD / 4 + 255) / 256, 256>>>(x, Xh, M * NXD / 4);
    cvt4_h_kernel<<<(int)(4 * (WN / 4) + 255) / 256, 256>>>(
        W_q, W_k, W_v, W_o, Wh, (int)(WN / 4));

    // Wvo = Wo @ Wv  (NN: A=Wo half, B=Wv half n-contiguous) -> half
    {
        dim3 g(NHD / 128, NHD / 128, 1);
        gemm_h_nn<<<g, 256, NN_SMEM>>>(Wh + 3 * WN, Wh + 2 * WN, Wvo,
                                       nullptr, 0,
                                       NHD, NXD, NHD, NHD, NXD, 0, 0, 0);
    }
    // Stacked QKV: Q,K from Wh slots 0/1; V' = x @ Wvo^T via Bg2
    {
        dim3 g(NQKV / 128, M / 128, 1);
        gemm_h<<<g, 256, NT_SMEM>>>(Xh, Wh, Wvo, nullptr, Qh, Kh, Vh, 1,
                                    nullptr, 0,
                                    M, NQKV, NXD, NXD, NXD, 1.f, 0, 0, 0);
    }
    // P[b] = exp(Q_b K_b^T / sqrt(T) - 4)  (half) + row sums via atomics
    {
        dim3 g(TD / 128, TD / 128, BD);
        gemm_h<<<g, 256, NT_SMEM>>>(Qh, Kh, nullptr, Ph,
                                    nullptr, nullptr, nullptr, 0,
                                    Sm, 1,
                                    TD, TD, NHD, NHD, NHD, scale,
                                    TN, TN, TT);
    }
    // out[b] = (P_b @ V'_b) / rowsums   (final f32 output; O GEMM folded away)
    {
        dim3 g(NHD / 128, TD / 128, BD);
        gemm_h_nn<<<g, 256, NN_SMEM>>>(Ph, Vh, out, Sm, 1,
                                       TD, NHD, TD, TD, NHD,
                                       TT, TN, TN);
    }
}